// round 7
// baseline (speedup 1.0000x reference)
#include <cuda_runtime.h>
#include <cuda_bf16.h>
#include <cstddef>
#include <cstdint>

typedef unsigned long long u64;
typedef unsigned int u32;
typedef __nv_bfloat16 bf16;

#define NCTA 148
#define NTHR 128

// smem chunk layout (bytes)
#define ASZ 18432   // 128 rows * 144
#define BSZ 9216    // 64 rows * 144
#define OFF_AL 18432
#define OFF_BH 36864
#define OFF_BL 46080
#define BUFSZ 55296

// ---------------- device scratch ----------------
__device__ float g_Xpre[(size_t)512 * 64 * 3072];  // [t][b][3072]
__device__ float g_H2[(size_t)512 * 64 * 1024];    // [t][b][1024]
__device__ float g_hbuf[2][3][65536];              // fp32 h (parity, layer) [b][n]
__device__ float g_z[3][65536];                    // z gate [b][n]
__device__ __align__(16) bf16 g_hbH[2][3][65536];  // h bf16 hi
__device__ __align__(16) bf16 g_hbL[2][3][65536];  // h bf16 lo
__device__ __align__(16) bf16 g_rhH[3][65536];     // r*h bf16 hi
__device__ __align__(16) bf16 g_rhL[3][65536];     // r*h bf16 lo
__device__ __align__(16) bf16 g_WhH[(size_t)3 * 3072 * 1024];  // Wh (l0=Wh0, l1/2=Whr)
__device__ __align__(16) bf16 g_WhL[(size_t)3 * 3072 * 1024];
__device__ __align__(16) bf16 g_WxH[(size_t)2 * 3072 * 1024];  // Wxr
__device__ __align__(16) bf16 g_WxL[(size_t)2 * 3072 * 1024];
__device__ unsigned g_cnt;
__device__ volatile unsigned g_gen;

// ---------------- generic helpers ----------------
__device__ __forceinline__ u64 ffma2(u64 a, u64 b, u64 c) {
    u64 d;
    asm("fma.rn.f32x2 %0, %1, %2, %3;" : "=l"(d) : "l"(a), "l"(b), "l"(c));
    return d;
}
__device__ __forceinline__ float psum(u64 a) {
    float2 f = *reinterpret_cast<float2*>(&a);
    return f.x + f.y;
}
__device__ __forceinline__ float sigm(float x) { return 1.f / (1.f + __expf(-x)); }

__device__ __forceinline__ void gridbar() {
    __syncthreads();
    if (threadIdx.x == 0) {
        unsigned old = g_gen;
        __threadfence();
        if (atomicAdd(&g_cnt, 1u) == NCTA - 1) {
            g_cnt = 0;
            __threadfence();
            g_gen = old + 1;
        } else {
            while (g_gen == old) __nanosleep(32);
            __threadfence();
        }
    }
    __syncthreads();
}

// ---------------- mma / ldmatrix / cp.async primitives (sm_80+ PTX) ----------------
__device__ __forceinline__ u32 smem_u32(const void* p) {
    u32 a;
    asm("{ .reg .u64 t; cvta.to.shared.u64 t, %1; cvt.u32.u64 %0, t; }" : "=r"(a) : "l"(p));
    return a;
}
__device__ __forceinline__ void mma16816(float* d, const u32* a, const u32* b) {
    asm volatile(
        "mma.sync.aligned.m16n8k16.row.col.f32.bf16.bf16.f32 "
        "{%0,%1,%2,%3}, {%4,%5,%6,%7}, {%8,%9}, {%0,%1,%2,%3};"
        : "+f"(d[0]), "+f"(d[1]), "+f"(d[2]), "+f"(d[3])
        : "r"(a[0]), "r"(a[1]), "r"(a[2]), "r"(a[3]), "r"(b[0]), "r"(b[1]));
}
__device__ __forceinline__ void ldm4(u32& r0, u32& r1, u32& r2, u32& r3, u32 addr) {
    asm volatile("ldmatrix.sync.aligned.m8n8.x4.shared.b16 {%0,%1,%2,%3}, [%4];"
                 : "=r"(r0), "=r"(r1), "=r"(r2), "=r"(r3) : "r"(addr));
}
__device__ __forceinline__ void cpa(u32 dst, const void* src) {
    asm volatile("cp.async.cg.shared.global [%0], [%1], 16;" :: "r"(dst), "l"(src) : "memory");
}
__device__ __forceinline__ void cp_commit() { asm volatile("cp.async.commit_group;" ::: "memory"); }
__device__ __forceinline__ void cp_wait0() { asm volatile("cp.async.wait_group 0;" ::: "memory"); }
__device__ __forceinline__ void cp_wait1() { asm volatile("cp.async.wait_group 1;" ::: "memory"); }

// issue one K=64 chunk: A[128x64] hi+lo, B[64x64] hi+lo -> smem buffer (cp.async)
__device__ __forceinline__ void issue_chunk(u32 sbuf, const bf16* __restrict__ AH,
                                            const bf16* __restrict__ AL,
                                            const bf16* __restrict__ BH,
                                            const bf16* __restrict__ BL, int kc, int tid) {
    const bf16* ah = AH + kc * 64;
    const bf16* al = AL + kc * 64;
    const bf16* bh = BH + kc * 64;
    const bf16* bl = BL + kc * 64;
#pragma unroll
    for (int it = 0; it < 8; it++) {
        int idx = tid + 128 * it;
        int row = idx >> 3, c16 = idx & 7;
        u32 d = sbuf + row * 144 + c16 * 16;
        size_t so = (size_t)row * 1024 + c16 * 8;
        cpa(d, ah + so);
        cpa(d + OFF_AL, al + so);
    }
#pragma unroll
    for (int it = 0; it < 4; it++) {
        int idx = tid + 128 * it;
        int row = idx >> 3, c16 = idx & 7;
        u32 d = sbuf + OFF_BH + row * 144 + c16 * 16;
        size_t so = (size_t)row * 1024 + c16 * 8;
        cpa(d, bh + so);
        cpa(d + (OFF_BL - OFF_BH), bl + so);
    }
}

// compute one K=64 chunk from smem buffer into register accumulators
__device__ __forceinline__ void mma_chunk(u32 sbuf, float (&acc)[2][8][4], int wid, int lane) {
    const int arow = ((lane >> 3) & 1) * 8 + (lane & 7);
    const int akk = ((lane >> 4) & 1) * 8;
    const int brow = ((lane >> 4) & 1) * 8 + (lane & 7);
    const int bkk = ((lane >> 3) & 1) * 8;
#pragma unroll
    for (int ks = 0; ks < 4; ks++) {
        int kOff = ks * 16;
        u32 aH[2][4], aL[2][4];
#pragma unroll
        for (int mt = 0; mt < 2; mt++) {
            int row = wid * 32 + mt * 16 + arow;
            u32 ad = sbuf + row * 144 + (kOff + akk) * 2;
            ldm4(aH[mt][0], aH[mt][1], aH[mt][2], aH[mt][3], ad);
            ldm4(aL[mt][0], aL[mt][1], aL[mt][2], aL[mt][3], ad + OFF_AL);
        }
        u32 bH[8][2], bL[8][2];
#pragma unroll
        for (int p = 0; p < 4; p++) {
            int nrow = p * 16 + brow;
            u32 bd = sbuf + OFF_BH + nrow * 144 + (kOff + bkk) * 2;
            u32 r0, r1, r2, r3;
            ldm4(r0, r1, r2, r3, bd);
            bH[2 * p][0] = r0; bH[2 * p][1] = r1; bH[2 * p + 1][0] = r2; bH[2 * p + 1][1] = r3;
            ldm4(r0, r1, r2, r3, bd + (OFF_BL - OFF_BH));
            bL[2 * p][0] = r0; bL[2 * p][1] = r1; bL[2 * p + 1][0] = r2; bL[2 * p + 1][1] = r3;
        }
#pragma unroll
        for (int mt = 0; mt < 2; mt++)
#pragma unroll
            for (int nt = 0; nt < 8; nt++) {
                mma16816(acc[mt][nt], aH[mt], bH[nt]);
                mma16816(acc[mt][nt], aH[mt], bL[nt]);
                mma16816(acc[mt][nt], aL[mt], bH[nt]);
            }
    }
}

// full source: acc += W[128 x 1024] * act[64 x 1024]^T (hi/lo split, 16 chunks, pipelined)
__device__ __forceinline__ void run_source(const bf16* __restrict__ AH, const bf16* __restrict__ AL,
                                           const bf16* __restrict__ BH, const bf16* __restrict__ BL,
                                           u32 sm0, float (&acc)[2][8][4], int tid, int wid,
                                           int lane) {
    issue_chunk(sm0, AH, AL, BH, BL, 0, tid);
    cp_commit();
    for (int c = 0; c < 16; c++) {
        if (c + 1 < 16) {
            issue_chunk(sm0 + ((c + 1) & 1) * BUFSZ, AH, AL, BH, BL, c + 1, tid);
            cp_commit();
            cp_wait1();
        } else {
            cp_wait0();
        }
        __syncthreads();
        mma_chunk(sm0 + (c & 1) * BUFSZ, acc, wid, lane);
        __syncthreads();
    }
}

__device__ __forceinline__ void zero_acc(float (&acc)[2][8][4]) {
#pragma unroll
    for (int i = 0; i < 2; i++)
#pragma unroll
        for (int j = 0; j < 8; j++)
#pragma unroll
            for (int e = 0; e < 4; e++) acc[i][j][e] = 0.f;
}

// ---------------- SIMT f32x2 GEMM (xpre / yout) ----------------
__device__ __forceinline__ void gemm_tile(const float* __restrict__ A, int lda,
                                          const float* __restrict__ W, int ldw,
                                          float* __restrict__ C, int cld,
                                          const float* __restrict__ bias, int nch,
                                          u64* __restrict__ Sm) {
    const int tid = threadIdx.x, tx = tid & 15, ty = tid >> 4;
    u64 acc[8][8];
#pragma unroll
    for (int i = 0; i < 8; i++)
#pragma unroll
        for (int j = 0; j < 8; j++) acc[i][j] = 0ull;
    u64 rA[8], rB[16];
#pragma unroll
    for (int it = 0; it < 8; it++) {
        int idx = tid + 128 * it, row = idx >> 4, k8 = idx & 15;
        rA[it] = *reinterpret_cast<const u64*>(A + (size_t)row * lda + (k8 << 1));
    }
#pragma unroll
    for (int it = 0; it < 16; it++) {
        int idx = tid + 128 * it, row = idx >> 4, k8 = idx & 15;
        rB[it] = *reinterpret_cast<const u64*>(W + (size_t)row * ldw + (k8 << 1));
    }
    for (int c = 0; c < nch; c++) {
        u64* Ab = Sm + (c & 1) * 3072;
        u64* Bb = Ab + 1024;
#pragma unroll
        for (int it = 0; it < 8; it++) {
            int idx = tid + 128 * it, row = idx >> 4, k8 = idx & 15;
            Ab[(row << 4) + (k8 ^ ((row >> 3) & 15))] = rA[it];
        }
#pragma unroll
        for (int it = 0; it < 16; it++) {
            int idx = tid + 128 * it, row = idx >> 4, k8 = idx & 15;
            Bb[(row << 4) + (k8 ^ ((row >> 3) & 15))] = rB[it];
        }
        __syncthreads();
        if (c + 1 < nch) {
            const float* A2 = A + (c + 1) * 32;
            const float* W2 = W + (c + 1) * 32;
#pragma unroll
            for (int it = 0; it < 8; it++) {
                int idx = tid + 128 * it, row = idx >> 4, k8 = idx & 15;
                rA[it] = *reinterpret_cast<const u64*>(A2 + (size_t)row * lda + (k8 << 1));
            }
#pragma unroll
            for (int it = 0; it < 16; it++) {
                int idx = tid + 128 * it, row = idx >> 4, k8 = idx & 15;
                rB[it] = *reinterpret_cast<const u64*>(W2 + (size_t)row * ldw + (k8 << 1));
            }
        }
#pragma unroll
        for (int k8 = 0; k8 < 16; k8++) {
            u64 a2[8], b2[8];
#pragma unroll
            for (int i = 0; i < 8; i++) a2[i] = Ab[((ty * 8 + i) << 4) + (k8 ^ ty)];
#pragma unroll
            for (int j = 0; j < 8; j++) b2[j] = Bb[((tx * 8 + j) << 4) + (k8 ^ tx)];
#pragma unroll
            for (int i = 0; i < 8; i++)
#pragma unroll
                for (int j = 0; j < 8; j++) acc[i][j] = ffma2(a2[i], b2[j], acc[i][j]);
        }
    }
#pragma unroll
    for (int i = 0; i < 8; i++)
#pragma unroll
        for (int j = 0; j < 8; j++) {
            float v = psum(acc[i][j]);
            if (bias) v += bias[tx * 8 + j];
            C[(size_t)(ty * 8 + i) * cld + tx * 8 + j] = v;
        }
    __syncthreads();
}

// ---------------- kernels ----------------
__global__ void k_pad() {}

// weight fp32 -> bf16 hi/lo
__global__ void k_conv(const float* __restrict__ Wh0, const float* __restrict__ Whr,
                       const float* __restrict__ Wxr) {
    const size_t NWH = (size_t)3 * 3072 * 1024;
    const size_t NTOT = (size_t)5 * 3072 * 1024;
    for (size_t i = (size_t)blockIdx.x * blockDim.x + threadIdx.x; i < NTOT;
         i += (size_t)gridDim.x * blockDim.x) {
        float w;
        bf16 *H, *L;
        size_t o;
        if (i < NWH) {
            o = i;
            w = (i < (size_t)3072 * 1024) ? Wh0[i] : Whr[i - (size_t)3072 * 1024];
            H = g_WhH; L = g_WhL;
        } else {
            o = i - NWH;
            w = Wxr[o];
            H = g_WxH; L = g_WxL;
        }
        bf16 h = __float2bfloat16_rn(w);
        H[o] = h;
        L[o] = __float2bfloat16_rn(w - __bfloat162float(h));
    }
}

// Xpre[t][b][n] = x[b][t][:] . Wx0[n][:]   grid (24, 512)
__global__ __launch_bounds__(NTHR, 2) void k_xpre(const float* __restrict__ x,
                                                  const float* __restrict__ Wx0) {
    __shared__ __align__(16) u64 Sm[6144];
    int n0 = blockIdx.x * 128, s = blockIdx.y;
    gemm_tile(x + (size_t)s * 128, 512 * 128, Wx0 + (size_t)n0 * 128, 128,
              g_Xpre + (size_t)s * 64 * 3072 + n0, 3072, nullptr, 4, Sm);
}

// persistent wavefront GRU with mma.sync bf16-split GEMMs
__global__ __launch_bounds__(NTHR) void k_gru(const float* __restrict__ bh0,
                                              const float* __restrict__ bhr) {
    extern __shared__ __align__(16) char dsm[];
    const u32 sm0 = smem_u32(dsm);
    const int tid = threadIdx.x, wid = tid >> 5, lane = tid & 31;
    const int cta = blockIdx.x;
    const int gtid = cta * NTHR + tid;

    // zero initial states (fp32 + bf16 hi/lo, both parities)
    for (int i = gtid; i < 2 * 3 * 65536; i += NCTA * NTHR) {
        (&g_hbuf[0][0][0])[i] = 0.f;
        (&g_hbH[0][0][0])[i] = __float2bfloat16_rn(0.f);
        (&g_hbL[0][0][0])[i] = __float2bfloat16_rn(0.f);
    }
    gridbar();

    // roles: cta<48 -> zr (l=cta/16, tt=cta%16); cta in [48,72) -> g (l=(cta-48)/8, tt=%8)
    int role, l = 0, tt = 0;
    if (cta < 48) { role = 0; l = cta >> 4; tt = cta & 15; }
    else if (cta < 72) { role = 1; l = (cta - 48) >> 3; tt = (cta - 48) & 7; }
    else role = 2;
    const int n0 = tt * 128;
    const int rlo = lane >> 2, cb = (lane & 3) * 2;

    float acc[2][8][4];

    for (int w = 0; w < 514; ++w) {
        const int rd = w & 1, wb = rd ^ 1;
        const int t = w - l;
        const bool act = (role < 2) && t >= 0 && t < 512;

        // ======== P1 ========
        if (act && role == 0) {
            zero_acc(acc);
            if (l > 0) {
                const bf16* AH = g_WxH + ((size_t)(l - 1) * 3072 + n0) * 1024;
                const bf16* AL = g_WxL + ((size_t)(l - 1) * 3072 + n0) * 1024;
                run_source(AH, AL, g_hbH[rd][l - 1], g_hbL[rd][l - 1], sm0, acc, tid, wid, lane);
            }
            {
                const bf16* AH = g_WhH + ((size_t)l * 3072 + n0) * 1024;
                const bf16* AL = g_WhL + ((size_t)l * 3072 + n0) * 1024;
                run_source(AH, AL, g_hbH[rd][l], g_hbL[rd][l], sm0, acc, tid, wid, lane);
            }
            // epilogue: z (n<1024) or rh (n>=1024)
            const float* bias = (l == 0) ? bh0 : bhr + (l - 1) * 3072;
#pragma unroll
            for (int mt = 0; mt < 2; mt++)
#pragma unroll
                for (int half = 0; half < 2; half++) {
                    int n = n0 + wid * 32 + mt * 16 + half * 8 + rlo;
                    float bv = bias[n];
                    if (n < 1024) {
#pragma unroll
                        for (int nt = 0; nt < 8; nt++)
#pragma unroll
                            for (int e = 0; e < 2; e++) {
                                int b = nt * 8 + cb + e;
                                float v = acc[mt][nt][half * 2 + e] + bv;
                                if (l == 0) v += g_Xpre[((size_t)t * 64 + b) * 3072 + n];
                                g_z[l][b * 1024 + n] = sigm(v);
                            }
                    } else {
                        int nn = n - 1024;
#pragma unroll
                        for (int nt = 0; nt < 8; nt++)
#pragma unroll
                            for (int e = 0; e < 2; e++) {
                                int b = nt * 8 + cb + e;
                                float v = acc[mt][nt][half * 2 + e] + bv;
                                if (l == 0) v += g_Xpre[((size_t)t * 64 + b) * 3072 + n];
                                float rv = sigm(v) * g_hbuf[rd][l][b * 1024 + nn];
                                bf16 hi = __float2bfloat16_rn(rv);
                                g_rhH[l][b * 1024 + nn] = hi;
                                g_rhL[l][b * 1024 + nn] =
                                    __float2bfloat16_rn(rv - __bfloat162float(hi));
                            }
                    }
                }
        } else if (act && role == 1 && l > 0) {
            zero_acc(acc);
            const bf16* AH = g_WxH + ((size_t)(l - 1) * 3072 + 2048 + n0) * 1024;
            const bf16* AL = g_WxL + ((size_t)(l - 1) * 3072 + 2048 + n0) * 1024;
            run_source(AH, AL, g_hbH[rd][l - 1], g_hbL[rd][l - 1], sm0, acc, tid, wid, lane);
        }
        gridbar();

        // ======== P2 ========
        if (act && role == 1) {
            if (l == 0) zero_acc(acc);
            const bf16* AH = g_WhH + ((size_t)l * 3072 + 2048 + n0) * 1024;
            const bf16* AL = g_WhL + ((size_t)l * 3072 + 2048 + n0) * 1024;
            run_source(AH, AL, g_rhH[l], g_rhL[l], sm0, acc, tid, wid, lane);
            // epilogue: g gate + h update
            const float* bias = (l == 0) ? bh0 : bhr + (l - 1) * 3072;
#pragma unroll
            for (int mt = 0; mt < 2; mt++)
#pragma unroll
                for (int half = 0; half < 2; half++) {
                    int gc = n0 + wid * 32 + mt * 16 + half * 8 + rlo;
                    float bv = bias[2048 + gc];
#pragma unroll
                    for (int nt = 0; nt < 8; nt++)
#pragma unroll
                        for (int e = 0; e < 2; e++) {
                            int b = nt * 8 + cb + e;
                            float v = acc[mt][nt][half * 2 + e] + bv;
                            if (l == 0) v += g_Xpre[((size_t)t * 64 + b) * 3072 + 2048 + gc];
                            float gg = tanhf(v);
                            float z = g_z[l][b * 1024 + gc];
                            float hp = g_hbuf[rd][l][b * 1024 + gc];
                            float hn = z * hp + (1.f - z) * gg;
                            g_hbuf[wb][l][b * 1024 + gc] = hn;
                            bf16 hi = __float2bfloat16_rn(hn);
                            g_hbH[wb][l][b * 1024 + gc] = hi;
                            g_hbL[wb][l][b * 1024 + gc] =
                                __float2bfloat16_rn(hn - __bfloat162float(hi));
                            if (l == 2) g_H2[((size_t)t * 64 + b) * 1024 + gc] = hn;
                        }
                }
        }
        gridbar();
    }
}

// y[b][s][o] = H2[s][b][:] . Wout[o][:] + bout   grid (512)
__global__ __launch_bounds__(NTHR, 2) void k_yout(const float* __restrict__ Wout,
                                                  const float* __restrict__ bout,
                                                  float* __restrict__ out) {
    __shared__ __align__(16) u64 Sm[6144];
    int s = blockIdx.x;
    gemm_tile(g_H2 + (size_t)s * 64 * 1024, 1024, Wout, 1024,
              out + (size_t)s * 128, 512 * 128, bout, 32, Sm);
}

// hidden_state (B, L, H): layer l's final h in parity buffer l&1
__global__ void k_hout(float* __restrict__ out) {
    int i = blockIdx.x * 256 + threadIdx.x;
    if (i >= 3 * 64 * 1024) return;
    int l = i / (64 * 1024);
    int r = i % (64 * 1024);
    int b = r / 1024, n = r % 1024;
    out[(size_t)64 * 512 * 128 + ((size_t)b * 3 + l) * 1024 + n] = g_hbuf[l & 1][l][r];
}

extern "C" void kernel_launch(void* const* d_in, const int* in_sizes, int n_in,
                              void* d_out, int out_size) {
    const float* x = (const float*)d_in[0];
    const float* Wx0 = (const float*)d_in[1];
    const float* Wh0 = (const float*)d_in[2];
    const float* bh0 = (const float*)d_in[3];
    const float* Wxr = (const float*)d_in[4];
    const float* Whr = (const float*)d_in[5];
    const float* bhr = (const float*)d_in[6];
    const float* Wout = (const float*)d_in[7];
    const float* bout = (const float*)d_in[8];
    float* out = (float*)d_out;

    cudaFuncSetAttribute(k_gru, cudaFuncAttributeMaxDynamicSharedMemorySize, 2 * BUFSZ);

    k_pad<<<1, 32>>>();
    k_pad<<<1, 32>>>();
    k_conv<<<2048, 256>>>(Wh0, Whr, Wxr);
    k_xpre<<<dim3(24, 512), NTHR>>>(x, Wx0);
    k_gru<<<NCTA, NTHR, 2 * BUFSZ>>>(bh0, bhr);
    k_yout<<<512, NTHR>>>(Wout, bout, out);
    k_hout<<<(3 * 64 * 1024 + 255) / 256, 256>>>(out);
}